// round 1
// baseline (speedup 1.0000x reference)
#include <cuda_runtime.h>
#include <math.h>

#define T_TOK 8192
#define DIM   2048
#define NE    8
#define RK    16
#define ER    128   // NE*RK

// Scratch (no allocations allowed)
__device__ int   g_idx[T_TOK];
__device__ float g_w[T_TOK];
__device__ float g_hmask[T_TOK * ER];   // 4 MB

__device__ __forceinline__ float gelu_exact(float v) {
    return 0.5f * v * (1.0f + erff(v * 0.7071067811865476f));
}

// ---------------------------------------------------------------------------
// Kernel 1: router. One warp per token. gate_w staged through smem (2 phases).
// Writes probs to d_out tail region, idx/w to scratch.
// ---------------------------------------------------------------------------
__global__ __launch_bounds__(256) void router_kernel(
    const float* __restrict__ x,
    const float* __restrict__ gw,
    const float* __restrict__ gb,
    float* __restrict__ probs)
{
    __shared__ float sgw[NE][DIM / 2];   // 32 KB
    const int warp = threadIdx.x >> 5;
    const int lane = threadIdx.x & 31;
    const int t    = blockIdx.x * 8 + warp;
    const float* xr = x + (size_t)t * DIM;

    float acc[NE];
#pragma unroll
    for (int e = 0; e < NE; e++) acc[e] = 0.f;

#pragma unroll
    for (int ph = 0; ph < 2; ph++) {
        const int k0 = ph * (DIM / 2);
        for (int i = threadIdx.x; i < NE * (DIM / 2); i += 256) {
            int e = i / (DIM / 2), k = i - e * (DIM / 2);
            sgw[e][k] = gw[e * DIM + k0 + k];
        }
        __syncthreads();
        for (int k = lane; k < DIM / 2; k += 32) {
            float xv = xr[k0 + k];
#pragma unroll
            for (int e = 0; e < NE; e++) acc[e] += xv * sgw[e][k];
        }
        __syncthreads();
    }
#pragma unroll
    for (int e = 0; e < NE; e++) {
#pragma unroll
        for (int o = 16; o > 0; o >>= 1)
            acc[e] += __shfl_xor_sync(0xffffffffu, acc[e], o);
    }
    if (lane == 0) {
        float m = -1e30f;
#pragma unroll
        for (int e = 0; e < NE; e++) { acc[e] += gb[e]; m = fmaxf(m, acc[e]); }
        float p[NE], s = 0.f;
#pragma unroll
        for (int e = 0; e < NE; e++) { p[e] = __expf(acc[e] - m); s += p[e]; }
        float inv = 1.f / s;
        int best = 0; float bp = -1.f;
#pragma unroll
        for (int e = 0; e < NE; e++) {
            p[e] *= inv;
            probs[t * NE + e] = p[e];
            if (p[e] > bp) { bp = p[e]; best = e; }   // strict > keeps first max
        }
        g_idx[t] = best;
        g_w[t]   = bp;
    }
}

// ---------------------------------------------------------------------------
// Kernel 2: h_masked = mask_sel(w * gelu(x @ lora_A_all)).  M=8192, N=128, K=2048.
// lora_A layout: [E, D, R], element (e,k,r) at e*D*R + k*R + r.
// ---------------------------------------------------------------------------
__global__ __launch_bounds__(256) void loraA_kernel(
    const float* __restrict__ x,
    const float* __restrict__ lA)
{
    __shared__ float As[16][132];
    __shared__ float Bs[16][132];
    const int tid = threadIdx.x;
    const int t0  = blockIdx.x * 128;
    const int tx  = tid & 15;
    const int ty  = tid >> 4;

    float acc[8][8];
#pragma unroll
    for (int i = 0; i < 8; i++)
#pragma unroll
        for (int j = 0; j < 8; j++) acc[i][j] = 0.f;

    const int n       = tid & 127;
    const int eb_base = (n >> 4) * (DIM * RK) + (n & 15);

    for (int k0 = 0; k0 < DIM; k0 += 16) {
#pragma unroll
        for (int i = 0; i < 2; i++) {
            int idx = tid + i * 256;
            int row = idx >> 2, kq = (idx & 3) * 4;
            float4 v = *(const float4*)(x + (size_t)(t0 + row) * DIM + k0 + kq);
            As[kq][row] = v.x; As[kq + 1][row] = v.y;
            As[kq + 2][row] = v.z; As[kq + 3][row] = v.w;
        }
#pragma unroll
        for (int i = 0; i < 8; i++) {
            int kk = (tid >> 7) + i * 2;
            Bs[kk][n] = lA[eb_base + (k0 + kk) * RK];
        }
        __syncthreads();
#pragma unroll
        for (int kk = 0; kk < 16; kk++) {
            float4 a0 = *(float4*)&As[kk][ty * 8];
            float4 a1 = *(float4*)&As[kk][ty * 8 + 4];
            float4 b0 = *(float4*)&Bs[kk][tx * 8];
            float4 b1 = *(float4*)&Bs[kk][tx * 8 + 4];
            float a[8] = {a0.x, a0.y, a0.z, a0.w, a1.x, a1.y, a1.z, a1.w};
            float b[8] = {b0.x, b0.y, b0.z, b0.w, b1.x, b1.y, b1.z, b1.w};
#pragma unroll
            for (int i = 0; i < 8; i++)
#pragma unroll
                for (int j = 0; j < 8; j++) acc[i][j] += a[i] * b[j];
        }
        __syncthreads();
    }

    const int e = tx >> 1;   // all 8 cols of this thread lie in one expert block
#pragma unroll
    for (int i = 0; i < 8; i++) {
        int t = t0 + ty * 8 + i;
        int sel = (g_idx[t] == e);
        float wv = g_w[t];
#pragma unroll
        for (int j = 0; j < 8; j++) {
            float v = sel ? wv * gelu_exact(acc[i][j]) : 0.f;
            g_hmask[(size_t)t * ER + tx * 8 + j] = v;
        }
    }
}

// ---------------------------------------------------------------------------
// Kernel 3: out = gelu(x @ base_w^T + b) + h_masked @ B_flat
// base_w: [D, D] row-major (both operands K-contiguous).
// B_flat = lora_B viewed as [128, 2048], n contiguous.
// ---------------------------------------------------------------------------
__global__ __launch_bounds__(256) void main_kernel(
    const float* __restrict__ x,
    const float* __restrict__ bw,
    const float* __restrict__ bb,
    const float* __restrict__ lB,
    float* __restrict__ out)
{
    __shared__ float As[16][132];
    __shared__ float Bs[16][132];
    const int tid = threadIdx.x;
    const int n0  = blockIdx.x * 128;
    const int t0  = blockIdx.y * 128;
    const int tx  = tid & 15;
    const int ty  = tid >> 4;

    float acc[8][8];
#pragma unroll
    for (int i = 0; i < 8; i++)
#pragma unroll
        for (int j = 0; j < 8; j++) acc[i][j] = 0.f;

    // ---- base GEMM: K = 2048 ----
    for (int k0 = 0; k0 < DIM; k0 += 16) {
#pragma unroll
        for (int i = 0; i < 2; i++) {
            int idx = tid + i * 256;
            int row = idx >> 2, kq = (idx & 3) * 4;
            float4 v = *(const float4*)(x + (size_t)(t0 + row) * DIM + k0 + kq);
            As[kq][row] = v.x; As[kq + 1][row] = v.y;
            As[kq + 2][row] = v.z; As[kq + 3][row] = v.w;
        }
#pragma unroll
        for (int i = 0; i < 2; i++) {
            int idx = tid + i * 256;
            int row = idx >> 2, kq = (idx & 3) * 4;
            float4 v = *(const float4*)(bw + (size_t)(n0 + row) * DIM + k0 + kq);
            Bs[kq][row] = v.x; Bs[kq + 1][row] = v.y;
            Bs[kq + 2][row] = v.z; Bs[kq + 3][row] = v.w;
        }
        __syncthreads();
#pragma unroll
        for (int kk = 0; kk < 16; kk++) {
            float4 a0 = *(float4*)&As[kk][ty * 8];
            float4 a1 = *(float4*)&As[kk][ty * 8 + 4];
            float4 b0 = *(float4*)&Bs[kk][tx * 8];
            float4 b1 = *(float4*)&Bs[kk][tx * 8 + 4];
            float a[8] = {a0.x, a0.y, a0.z, a0.w, a1.x, a1.y, a1.z, a1.w};
            float b[8] = {b0.x, b0.y, b0.z, b0.w, b1.x, b1.y, b1.z, b1.w};
#pragma unroll
            for (int i = 0; i < 8; i++)
#pragma unroll
                for (int j = 0; j < 8; j++) acc[i][j] += a[i] * b[j];
        }
        __syncthreads();
    }

    // ---- bias + exact GELU on the base result ----
#pragma unroll
    for (int j = 0; j < 8; j++) {
        float bbv = bb[n0 + tx * 8 + j];
#pragma unroll
        for (int i = 0; i < 8; i++) acc[i][j] = gelu_exact(acc[i][j] + bbv);
    }

    // ---- LoRA-B add: K = 128 over h_masked @ B_flat ----
    for (int k0 = 0; k0 < ER; k0 += 16) {
#pragma unroll
        for (int i = 0; i < 2; i++) {
            int idx = tid + i * 256;
            int row = idx >> 2, kq = (idx & 3) * 4;
            float4 v = *(const float4*)(g_hmask + (size_t)(t0 + row) * ER + k0 + kq);
            As[kq][row] = v.x; As[kq + 1][row] = v.y;
            As[kq + 2][row] = v.z; As[kq + 3][row] = v.w;
        }
#pragma unroll
        for (int i = 0; i < 2; i++) {
            int idx = tid + i * 256;
            int kk = idx >> 5, nq = (idx & 31) * 4;
            float4 v = *(const float4*)(lB + (size_t)(k0 + kk) * DIM + n0 + nq);
            Bs[kk][nq] = v.x; Bs[kk][nq + 1] = v.y;
            Bs[kk][nq + 2] = v.z; Bs[kk][nq + 3] = v.w;
        }
        __syncthreads();
#pragma unroll
        for (int kk = 0; kk < 16; kk++) {
            float4 a0 = *(float4*)&As[kk][ty * 8];
            float4 a1 = *(float4*)&As[kk][ty * 8 + 4];
            float4 b0 = *(float4*)&Bs[kk][tx * 8];
            float4 b1 = *(float4*)&Bs[kk][tx * 8 + 4];
            float a[8] = {a0.x, a0.y, a0.z, a0.w, a1.x, a1.y, a1.z, a1.w};
            float b[8] = {b0.x, b0.y, b0.z, b0.w, b1.x, b1.y, b1.z, b1.w};
#pragma unroll
            for (int i = 0; i < 8; i++)
#pragma unroll
                for (int j = 0; j < 8; j++) acc[i][j] += a[i] * b[j];
        }
        __syncthreads();
    }

    // ---- write ----
#pragma unroll
    for (int i = 0; i < 8; i++) {
        int t = t0 + ty * 8 + i;
        float4 o0 = make_float4(acc[i][0], acc[i][1], acc[i][2], acc[i][3]);
        float4 o1 = make_float4(acc[i][4], acc[i][5], acc[i][6], acc[i][7]);
        *(float4*)(out + (size_t)t * DIM + n0 + tx * 8)     = o0;
        *(float4*)(out + (size_t)t * DIM + n0 + tx * 8 + 4) = o1;
    }
}

// ---------------------------------------------------------------------------
extern "C" void kernel_launch(void* const* d_in, const int* in_sizes, int n_in,
                              void* d_out, int out_size)
{
    const float* x  = (const float*)d_in[0];
    const float* gw = (const float*)d_in[1];
    const float* gb = (const float*)d_in[2];
    const float* bw = (const float*)d_in[3];
    const float* bb = (const float*)d_in[4];
    const float* lA = (const float*)d_in[5];
    const float* lB = (const float*)d_in[6];

    float* out   = (float*)d_out;                       // [4,2048,2048]
    float* probs = out + (size_t)T_TOK * (size_t)DIM;   // [8192, 8] appended

    router_kernel<<<T_TOK / 8, 256>>>(x, gw, gb, probs);
    loraA_kernel<<<T_TOK / 128, 256>>>(x, lA);
    main_kernel<<<dim3(DIM / 128, T_TOK / 128), 256>>>(x, bw, bb, lB, out);
}

// round 3
// speedup vs baseline: 3.6666x; 3.6666x over previous
#include <cuda_runtime.h>
#include <cuda_bf16.h>
#include <math.h>
#include <stdint.h>

#define T_TOK 8192
#define DIM   2048
#define NE    8
#define RK    16
#define ER    128

// ---------------- device scratch ----------------
__device__ int   g_idx[T_TOK];
__device__ float g_w[T_TOK];
__device__ __align__(256) __nv_bfloat16 g_xhi[T_TOK * DIM];
__device__ __align__(256) __nv_bfloat16 g_xlo[T_TOK * DIM];
__device__ __align__(256) __nv_bfloat16 g_whi[DIM * DIM];
__device__ __align__(256) __nv_bfloat16 g_wlo[DIM * DIM];
__device__ __align__(256) __nv_bfloat16 g_lAt[ER * DIM];   // [n=e*16+r][k]
__device__ __align__(256) __nv_bfloat16 g_lBt[DIM * ER];   // [n][k2]
__device__ __align__(256) __nv_bfloat16 g_hm[T_TOK * ER];  // masked scaled h

__device__ __forceinline__ float gelu_exact(float v) {
    return 0.5f * v * (1.0f + erff(v * 0.7071067811865476f));
}
__device__ __forceinline__ uint32_t smem_u32(const void* p) {
    uint32_t a;
    asm("{ .reg .u64 t; cvta.to.shared.u64 t, %1; cvt.u32.u64 %0, t; }" : "=r"(a) : "l"(p));
    return a;
}
#define CP_ASYNC16(dst, src) asm volatile("cp.async.cg.shared.global [%0], [%1], 16;" :: "r"(dst), "l"(src))
#define CP_COMMIT()          asm volatile("cp.async.commit_group;" ::: "memory")
#define CP_WAIT(n)           asm volatile("cp.async.wait_group %0;" :: "n"(n) : "memory")

__device__ __forceinline__ void ldsm4(uint32_t* r, uint32_t addr) {
    asm volatile("ldmatrix.sync.aligned.m8n8.x4.shared.b16 {%0,%1,%2,%3}, [%4];"
        : "=r"(r[0]), "=r"(r[1]), "=r"(r[2]), "=r"(r[3]) : "r"(addr));
}
__device__ __forceinline__ void mma16816(float* d, const uint32_t* a, const uint32_t* b) {
    asm volatile("mma.sync.aligned.m16n8k16.row.col.f32.bf16.bf16.f32 "
        "{%0,%1,%2,%3}, {%4,%5,%6,%7}, {%8,%9}, {%0,%1,%2,%3};"
        : "+f"(d[0]), "+f"(d[1]), "+f"(d[2]), "+f"(d[3])
        : "r"(a[0]), "r"(a[1]), "r"(a[2]), "r"(a[3]), "r"(b[0]), "r"(b[1]));
}

// smem tile: 128 rows x 64B (32 bf16), swizzled: chunk ^= (row>>1)&3
__device__ __forceinline__ uint32_t sw_off(int row, int chunk) {
    return (uint32_t)(row * 64 + ((chunk ^ ((row >> 1) & 3)) << 4));
}

// ---------------- prep kernels ----------------
__global__ __launch_bounds__(256) void split2_kernel(
    const float* __restrict__ src, __nv_bfloat16* __restrict__ hi,
    __nv_bfloat16* __restrict__ lo, int n4)
{
    int i = blockIdx.x * 256 + threadIdx.x;
    if (i >= n4) return;
    float4 v = ((const float4*)src)[i];
    float vv[4] = {v.x, v.y, v.z, v.w};
    __nv_bfloat16 h[4], l[4];
#pragma unroll
    for (int k = 0; k < 4; k++) {
        h[k] = __float2bfloat16_rn(vv[k]);
        l[k] = __float2bfloat16_rn(vv[k] - __bfloat162float(h[k]));
    }
    ((uint2*)hi)[i] = *(uint2*)h;
    ((uint2*)lo)[i] = *(uint2*)l;
}
__global__ __launch_bounds__(256) void pack_lA_kernel(const float* __restrict__ lA) {
    int idx = blockIdx.x * 256 + threadIdx.x;
    int k = idx & (DIM - 1), n = idx >> 11;
    g_lAt[idx] = __float2bfloat16_rn(lA[(size_t)((n >> 4) * DIM + k) * RK + (n & 15)]);
}
__global__ __launch_bounds__(256) void pack_lB_kernel(const float* __restrict__ lB) {
    int idx = blockIdx.x * 256 + threadIdx.x;
    int k2 = idx & 127, n = idx >> 7;
    g_lBt[idx] = __float2bfloat16_rn(lB[(size_t)((k2 >> 4) * RK + (k2 & 15)) * DIM + n]);
}

// ---------------- router ----------------
__global__ __launch_bounds__(256) void router_kernel(
    const float* __restrict__ x, const float* __restrict__ gw,
    const float* __restrict__ gb, float* __restrict__ probs)
{
    __shared__ float sgw[NE][DIM / 2];
    const int warp = threadIdx.x >> 5, lane = threadIdx.x & 31;
    const int t = blockIdx.x * 8 + warp;
    const float* xr = x + (size_t)t * DIM;
    float acc[NE];
#pragma unroll
    for (int e = 0; e < NE; e++) acc[e] = 0.f;
#pragma unroll
    for (int ph = 0; ph < 2; ph++) {
        const int k0 = ph * (DIM / 2);
        for (int i = threadIdx.x; i < NE * (DIM / 2); i += 256) {
            int e = i / (DIM / 2), k = i - e * (DIM / 2);
            sgw[e][k] = gw[e * DIM + k0 + k];
        }
        __syncthreads();
        for (int k = lane; k < DIM / 2; k += 32) {
            float xv = xr[k0 + k];
#pragma unroll
            for (int e = 0; e < NE; e++) acc[e] += xv * sgw[e][k];
        }
        __syncthreads();
    }
#pragma unroll
    for (int e = 0; e < NE; e++)
#pragma unroll
        for (int o = 16; o > 0; o >>= 1) acc[e] += __shfl_xor_sync(0xffffffffu, acc[e], o);
    if (lane == 0) {
        float m = -1e30f;
#pragma unroll
        for (int e = 0; e < NE; e++) { acc[e] += gb[e]; m = fmaxf(m, acc[e]); }
        float p[NE], s = 0.f;
#pragma unroll
        for (int e = 0; e < NE; e++) { p[e] = __expf(acc[e] - m); s += p[e]; }
        float inv = 1.f / s;
        int best = 0; float bp = -1.f;
#pragma unroll
        for (int e = 0; e < NE; e++) {
            p[e] *= inv;
            probs[t * NE + e] = p[e];
            if (p[e] > bp) { bp = p[e]; best = e; }
        }
        g_idx[t] = best; g_w[t] = bp;
    }
}

// ---------------- LoRA-A mma kernel: g_hm = mask(w * gelu(xhi @ lAt^T)) ----------------
// M=8192 (BM=128 per CTA), N=128, K=2048. 3-stage pipeline, 16KB/stage.
__global__ __launch_bounds__(256, 2) void loraA_mma() {
    extern __shared__ char sm[];
    uint32_t sb = smem_u32(sm);
    const int tid = threadIdx.x, wid = tid >> 5, lane = tid & 31;
    const int t0 = blockIdx.x * 128;
    const int warp_m = (wid & 3) * 32, warp_n = (wid >> 2) * 64;
    const int lrow = tid >> 2, lc = tid & 3;

    float acc[2][8][4];
#pragma unroll
    for (int a = 0; a < 2; a++)
#pragma unroll
        for (int b = 0; b < 8; b++)
#pragma unroll
            for (int c = 0; c < 4; c++) acc[a][b][c] = 0.f;

#define LA_STAGE 16384
#define LA_ISSUE(s, k0) do {                                                  \
    uint32_t st = sb + (uint32_t)(s) * LA_STAGE;                              \
    _Pragma("unroll")                                                         \
    for (int i = 0; i < 2; i++) {                                             \
        int row = lrow + i * 64;                                              \
        CP_ASYNC16(st + sw_off(row, lc), g_xhi + (size_t)(t0 + row) * DIM + (k0) + lc * 8); \
        CP_ASYNC16(st + 8192 + sw_off(row, lc), g_lAt + (size_t)row * DIM + (k0) + lc * 8); \
    }                                                                         \
    CP_COMMIT();                                                              \
} while (0)

    LA_ISSUE(0, 0);
    LA_ISSUE(1, 32);
    for (int c = 0; c < 64; c++) {
        if (c == 63) { CP_WAIT(0); } else { CP_WAIT(1); }
        __syncthreads();
        if (c + 2 < 64) LA_ISSUE((c + 2) % 3, (c + 2) * 32);
        uint32_t base = sb + (uint32_t)(c % 3) * LA_STAGE;
#pragma unroll
        for (int kk = 0; kk < 2; kk++) {
            uint32_t ah[2][4];
#pragma unroll
            for (int mi = 0; mi < 2; mi++) {
                int r = warp_m + mi * 16 + (lane & 15);
                ldsm4(ah[mi], base + sw_off(r, kk * 2 + (lane >> 4)));
            }
#pragma unroll
            for (int p = 0; p < 4; p++) {
                uint32_t bh[4];
                int r = warp_n + p * 16 + (lane & 7) + ((lane >> 4) << 3);
                ldsm4(bh, base + 8192 + sw_off(r, kk * 2 + ((lane >> 3) & 1)));
#pragma unroll
                for (int mi = 0; mi < 2; mi++) {
                    mma16816(acc[mi][p * 2], ah[mi], bh);
                    mma16816(acc[mi][p * 2 + 1], ah[mi], bh + 2);
                }
            }
        }
        __syncthreads();
    }

    // epilogue: mask + scale + gelu -> bf16 g_hm
#pragma unroll
    for (int mi = 0; mi < 2; mi++) {
#pragma unroll
        for (int h = 0; h < 2; h++) {
            int t = t0 + warp_m + mi * 16 + (lane >> 2) + h * 8;
            int se = g_idx[t];
            float wv = g_w[t];
#pragma unroll
            for (int nt = 0; nt < 8; nt++) {
                int col = warp_n + nt * 8 + (lane & 3) * 2;
                float v0 = ((col >> 4) == se) ? wv * gelu_exact(acc[mi][nt][h * 2]) : 0.f;
                float v1 = (((col + 1) >> 4) == se) ? wv * gelu_exact(acc[mi][nt][h * 2 + 1]) : 0.f;
                __nv_bfloat162 p2 = __floats2bfloat162_rn(v0, v1);
                *(uint32_t*)(g_hm + (size_t)t * ER + col) = *(uint32_t*)&p2;
            }
        }
    }
}

// ---------------- main mma kernel ----------------
// BM=128, BN=128, K=2048, 3-term bf16 split; fused LoRA-B tail (K=128) + epilogue.
#define ST_XHI 0
#define ST_XLO 8192
#define ST_WHI 16384
#define ST_WLO 24576
#define STAGE_B 32768

__global__ __launch_bounds__(256, 2) void main_mma(
    const float* __restrict__ bb, float* __restrict__ out)
{
    extern __shared__ char sm[];
    uint32_t sb = smem_u32(sm);
    const int tid = threadIdx.x, wid = tid >> 5, lane = tid & 31;
    const int n0 = blockIdx.x * 128, t0 = blockIdx.y * 128;
    const int warp_m = (wid & 3) * 32, warp_n = (wid >> 2) * 64;
    const int lrow = tid >> 2, lc = tid & 3;

    float acc[2][8][4];
#pragma unroll
    for (int a = 0; a < 2; a++)
#pragma unroll
        for (int b = 0; b < 8; b++)
#pragma unroll
            for (int c = 0; c < 4; c++) acc[a][b][c] = 0.f;

#define MN_ISSUE(s, k0) do {                                                  \
    uint32_t st = sb + (uint32_t)(s) * STAGE_B;                               \
    _Pragma("unroll")                                                         \
    for (int i = 0; i < 2; i++) {                                             \
        int row = lrow + i * 64;                                              \
        size_t gx = (size_t)(t0 + row) * DIM + (k0) + lc * 8;                 \
        size_t gw_ = (size_t)(n0 + row) * DIM + (k0) + lc * 8;                \
        uint32_t so = sw_off(row, lc);                                        \
        CP_ASYNC16(st + ST_XHI + so, g_xhi + gx);                             \
        CP_ASYNC16(st + ST_XLO + so, g_xlo + gx);                             \
        CP_ASYNC16(st + ST_WHI + so, g_whi + gw_);                            \
        CP_ASYNC16(st + ST_WLO + so, g_wlo + gw_);                            \
    }                                                                         \
    CP_COMMIT();                                                              \
} while (0)

    MN_ISSUE(0, 0);
    MN_ISSUE(1, 32);
    for (int c = 0; c < 64; c++) {
        if (c == 63) { CP_WAIT(0); } else { CP_WAIT(1); }
        __syncthreads();
        if (c + 2 < 64) MN_ISSUE((c + 2) % 3, (c + 2) * 32);
        uint32_t base = sb + (uint32_t)(c % 3) * STAGE_B;
#pragma unroll
        for (int kk = 0; kk < 2; kk++) {
            uint32_t ah[2][4], al[2][4];
#pragma unroll
            for (int mi = 0; mi < 2; mi++) {
                int r = warp_m + mi * 16 + (lane & 15);
                uint32_t so = sw_off(r, kk * 2 + (lane >> 4));
                ldsm4(ah[mi], base + ST_XHI + so);
                ldsm4(al[mi], base + ST_XLO + so);
            }
#pragma unroll
            for (int p = 0; p < 4; p++) {
                uint32_t bh[4], bl[4];
                int r = warp_n + p * 16 + (lane & 7) + ((lane >> 4) << 3);
                uint32_t so = sw_off(r, kk * 2 + ((lane >> 3) & 1));
                ldsm4(bh, base + ST_WHI + so);
                ldsm4(bl, base + ST_WLO + so);
#pragma unroll
                for (int mi = 0; mi < 2; mi++) {
                    mma16816(acc[mi][p * 2],     ah[mi], bh);
                    mma16816(acc[mi][p * 2 + 1], ah[mi], bh + 2);
                    mma16816(acc[mi][p * 2],     ah[mi], bl);
                    mma16816(acc[mi][p * 2 + 1], ah[mi], bl + 2);
                    mma16816(acc[mi][p * 2],     al[mi], bh);
                    mma16816(acc[mi][p * 2 + 1], al[mi], bh + 2);
                }
            }
        }
        __syncthreads();
    }

    // ---- base epilogue: out = gelu(acc + bias) ----
#pragma unroll
    for (int mi = 0; mi < 2; mi++) {
#pragma unroll
        for (int h = 0; h < 2; h++) {
            int t = t0 + warp_m + mi * 16 + (lane >> 2) + h * 8;
            float* orow = out + (size_t)t * DIM + n0 + warp_n;
#pragma unroll
            for (int nt = 0; nt < 8; nt++) {
                int col = nt * 8 + (lane & 3) * 2;
                float b0 = __ldg(bb + n0 + warp_n + col);
                float b1 = __ldg(bb + n0 + warp_n + col + 1);
                float2 v;
                v.x = gelu_exact(acc[mi][nt][h * 2] + b0);
                v.y = gelu_exact(acc[mi][nt][h * 2 + 1] + b1);
                *(float2*)(orow + col) = v;
            }
        }
    }

    // ---- LoRA-B tail: acc = hm @ lBt^T (K=128), then out += acc ----
#pragma unroll
    for (int a = 0; a < 2; a++)
#pragma unroll
        for (int b = 0; b < 8; b++)
#pragma unroll
            for (int c = 0; c < 4; c++) acc[a][b][c] = 0.f;

    for (int c2 = 0; c2 < 4; c2++) {
        int k0 = c2 * 32;
        __syncthreads();   // protect stage-0 buffers from any lagging reader
#pragma unroll
        for (int i = 0; i < 2; i++) {
            int row = lrow + i * 64;
            uint32_t so = sw_off(row, lc);
            CP_ASYNC16(sb + ST_XHI + so, g_hm + (size_t)(t0 + row) * ER + k0 + lc * 8);
            CP_ASYNC16(sb + ST_WHI + so, g_lBt + (size_t)(n0 + row) * ER + k0 + lc * 8);
        }
        CP_COMMIT();
        CP_WAIT(0);
        __syncthreads();
#pragma unroll
        for (int kk = 0; kk < 2; kk++) {
            uint32_t ah[2][4];
#pragma unroll
            for (int mi = 0; mi < 2; mi++) {
                int r = warp_m + mi * 16 + (lane & 15);
                ldsm4(ah[mi], sb + ST_XHI + sw_off(r, kk * 2 + (lane >> 4)));
            }
#pragma unroll
            for (int p = 0; p < 4; p++) {
                uint32_t bh[4];
                int r = warp_n + p * 16 + (lane & 7) + ((lane >> 4) << 3);
                ldsm4(bh, sb + ST_WHI + sw_off(r, kk * 2 + ((lane >> 3) & 1)));
#pragma unroll
                for (int mi = 0; mi < 2; mi++) {
                    mma16816(acc[mi][p * 2], ah[mi], bh);
                    mma16816(acc[mi][p * 2 + 1], ah[mi], bh + 2);
                }
            }
        }
    }
#pragma unroll
    for (int mi = 0; mi < 2; mi++) {
#pragma unroll
        for (int h = 0; h < 2; h++) {
            int t = t0 + warp_m + mi * 16 + (lane >> 2) + h * 8;
            float* orow = out + (size_t)t * DIM + n0 + warp_n;
#pragma unroll
            for (int nt = 0; nt < 8; nt++) {
                int col = nt * 8 + (lane & 3) * 2;
                float2 v = *(float2*)(orow + col);
                v.x += acc[mi][nt][h * 2];
                v.y += acc[mi][nt][h * 2 + 1];
                *(float2*)(orow + col) = v;
            }
        }
    }
}

// ---------------------------------------------------------------------------
extern "C" void kernel_launch(void* const* d_in, const int* in_sizes, int n_in,
                              void* d_out, int out_size)
{
    const float* x  = (const float*)d_in[0];
    const float* gw = (const float*)d_in[1];
    const float* gb = (const float*)d_in[2];
    const float* bw = (const float*)d_in[3];
    const float* bb = (const float*)d_in[4];
    const float* lA = (const float*)d_in[5];
    const float* lB = (const float*)d_in[6];

    float* out   = (float*)d_out;
    float* probs = out + (size_t)T_TOK * (size_t)DIM;

    static int attr_done = 0;
    cudaFuncSetAttribute(main_mma, cudaFuncAttributeMaxDynamicSharedMemorySize, 3 * STAGE_B);
    cudaFuncSetAttribute(loraA_mma, cudaFuncAttributeMaxDynamicSharedMemorySize, 3 * LA_STAGE);
    (void)attr_done;

    __nv_bfloat16 *xhi, *xlo, *whi, *wlo;
    cudaGetSymbolAddress((void**)&xhi, g_xhi);
    cudaGetSymbolAddress((void**)&xlo, g_xlo);
    cudaGetSymbolAddress((void**)&whi, g_whi);
    cudaGetSymbolAddress((void**)&wlo, g_wlo);

    split2_kernel<<<T_TOK * DIM / 4 / 256, 256>>>(x, xhi, xlo, T_TOK * DIM / 4);
    split2_kernel<<<DIM * DIM / 4 / 256, 256>>>(bw, whi, wlo, DIM * DIM / 4);
    pack_lA_kernel<<<ER * DIM / 256, 256>>>(lA);
    pack_lB_kernel<<<DIM * ER / 256, 256>>>(lB);
    router_kernel<<<T_TOK / 8, 256>>>(x, gw, gb, probs);
    loraA_mma<<<T_TOK / 128, 256, 3 * LA_STAGE>>>();
    main_mma<<<dim3(DIM / 128, T_TOK / 128), 256, 3 * STAGE_B>>>(bb, out);
}

// round 4
// speedup vs baseline: 7.0108x; 1.9121x over previous
#include <cuda_runtime.h>
#include <cuda_fp16.h>
#include <math.h>
#include <stdint.h>

#define T_TOK 8192
#define DIM   2048
#define NE    8
#define RK    16
#define ER    128

// ---------------- device scratch ----------------
__device__ int   g_idx[T_TOK];
__device__ float g_w[T_TOK];
__device__ __align__(256) __half g_xh[T_TOK * DIM];
__device__ __align__(256) __half g_wh[DIM * DIM];
__device__ __align__(256) __half g_lAt[ER * DIM];   // [n=e*16+r][k]
__device__ __align__(256) __half g_lBt[DIM * ER];   // [n][k2]
__device__ __align__(256) __half g_hm[T_TOK * ER];  // masked scaled h

__device__ __forceinline__ float gelu_exact(float v) {
    return 0.5f * v * (1.0f + erff(v * 0.7071067811865476f));
}
__device__ __forceinline__ uint32_t smem_u32(const void* p) {
    uint32_t a;
    asm("{ .reg .u64 t; cvta.to.shared.u64 t, %1; cvt.u32.u64 %0, t; }" : "=r"(a) : "l"(p));
    return a;
}
#define CP_ASYNC16(dst, src) asm volatile("cp.async.cg.shared.global [%0], [%1], 16;" :: "r"(dst), "l"(src))
#define CP_COMMIT()          asm volatile("cp.async.commit_group;" ::: "memory")
#define CP_WAIT(n)           asm volatile("cp.async.wait_group %0;" :: "n"(n) : "memory")

__device__ __forceinline__ void ldsm4(uint32_t* r, uint32_t addr) {
    asm volatile("ldmatrix.sync.aligned.m8n8.x4.shared.b16 {%0,%1,%2,%3}, [%4];"
        : "=r"(r[0]), "=r"(r[1]), "=r"(r[2]), "=r"(r[3]) : "r"(addr));
}
__device__ __forceinline__ void mma16816(float* d, const uint32_t* a, const uint32_t* b) {
    asm volatile("mma.sync.aligned.m16n8k16.row.col.f32.f16.f16.f32 "
        "{%0,%1,%2,%3}, {%4,%5,%6,%7}, {%8,%9}, {%0,%1,%2,%3};"
        : "+f"(d[0]), "+f"(d[1]), "+f"(d[2]), "+f"(d[3])
        : "r"(a[0]), "r"(a[1]), "r"(a[2]), "r"(a[3]), "r"(b[0]), "r"(b[1]));
}

// smem tile: rows x 64B (32 halves), swizzled: chunk ^= (row>>1)&3
__device__ __forceinline__ uint32_t sw_off(int row, int chunk) {
    return (uint32_t)(row * 64 + ((chunk ^ ((row >> 1) & 3)) << 4));
}

// ---------------- fused x->fp16 convert + router ----------------
// One warp per token. Block = 8 tokens. gate_w in 64KB dynamic smem.
__global__ __launch_bounds__(256) void convx_router(
    const float* __restrict__ x, const float* __restrict__ gw,
    const float* __restrict__ gb, float* __restrict__ probs)
{
    extern __shared__ char smc[];
    float (*sgw)[DIM] = (float(*)[DIM])smc;
    const int warp = threadIdx.x >> 5, lane = threadIdx.x & 31;
    const int t = blockIdx.x * 8 + warp;
    const float* xr = x + (size_t)t * DIM;
    __half* xo = g_xh + (size_t)t * DIM;

    for (int i = threadIdx.x; i < NE * (DIM / 4); i += 256)
        ((float4*)smc)[i] = ((const float4*)gw)[i];
    __syncthreads();

    float acc[NE];
#pragma unroll
    for (int e = 0; e < NE; e++) acc[e] = 0.f;

#pragma unroll
    for (int i = 0; i < 16; i++) {
        int k = lane * 4 + i * 128;
        float4 v = *(const float4*)(xr + k);
        __half h[4] = {__float2half_rn(v.x), __float2half_rn(v.y),
                       __float2half_rn(v.z), __float2half_rn(v.w)};
        *(uint2*)(xo + k) = *(uint2*)h;
#pragma unroll
        for (int e = 0; e < NE; e++) {
            acc[e] += v.x * sgw[e][k] + v.y * sgw[e][k + 1]
                    + v.z * sgw[e][k + 2] + v.w * sgw[e][k + 3];
        }
    }
#pragma unroll
    for (int e = 0; e < NE; e++)
#pragma unroll
        for (int o = 16; o > 0; o >>= 1) acc[e] += __shfl_xor_sync(0xffffffffu, acc[e], o);
    if (lane == 0) {
        float m = -1e30f;
#pragma unroll
        for (int e = 0; e < NE; e++) { acc[e] += gb[e]; m = fmaxf(m, acc[e]); }
        float p[NE], s = 0.f;
#pragma unroll
        for (int e = 0; e < NE; e++) { p[e] = __expf(acc[e] - m); s += p[e]; }
        float inv = 1.f / s;
        int best = 0; float bp = -1.f;
#pragma unroll
        for (int e = 0; e < NE; e++) {
            p[e] *= inv;
            probs[t * NE + e] = p[e];
            if (p[e] > bp) { bp = p[e]; best = e; }
        }
        g_idx[t] = best; g_w[t] = bp;
    }
}

// ---------------- prep kernels ----------------
__global__ __launch_bounds__(256) void conv_w(const float* __restrict__ src, int n4) {
    int i = blockIdx.x * 256 + threadIdx.x;
    if (i >= n4) return;
    float4 v = ((const float4*)src)[i];
    __half h[4] = {__float2half_rn(v.x), __float2half_rn(v.y),
                   __float2half_rn(v.z), __float2half_rn(v.w)};
    ((uint2*)g_wh)[i] = *(uint2*)h;
}
__global__ __launch_bounds__(256) void pack_lA_kernel(const float* __restrict__ lA) {
    int idx = blockIdx.x * 256 + threadIdx.x;
    int k = idx & (DIM - 1), n = idx >> 11;
    g_lAt[idx] = __float2half_rn(lA[(size_t)((n >> 4) * DIM + k) * RK + (n & 15)]);
}
__global__ __launch_bounds__(256) void pack_lB_kernel(const float* __restrict__ lB) {
    int idx = blockIdx.x * 256 + threadIdx.x;
    int k2 = idx & 127, n = idx >> 7;
    g_lBt[idx] = __float2half_rn(lB[(size_t)((k2 >> 4) * RK + (k2 & 15)) * DIM + n]);
}

// ---------------- LoRA-A: g_hm = mask(w * gelu(xh @ lAt^T)) ----------------
// BM=128 per CTA, N=128, K=2048. 4-stage pipeline, 16KB/stage.
#define LA_STAGE 16384
__global__ __launch_bounds__(256, 2) void loraA_mma() {
    extern __shared__ char sm[];
    uint32_t sb = smem_u32(sm);
    const int tid = threadIdx.x, wid = tid >> 5, lane = tid & 31;
    const int t0 = blockIdx.x * 128;
    const int warp_m = (wid & 3) * 32, warp_n = (wid >> 2) * 64;
    const int lrow = tid >> 2, lc = tid & 3;

    float acc[2][8][4];
#pragma unroll
    for (int a = 0; a < 2; a++)
#pragma unroll
        for (int b = 0; b < 8; b++)
#pragma unroll
            for (int c = 0; c < 4; c++) acc[a][b][c] = 0.f;

#define LA_ISSUE(s, k0) do {                                                  \
    uint32_t st = sb + (uint32_t)(s) * LA_STAGE;                              \
    _Pragma("unroll")                                                         \
    for (int i = 0; i < 2; i++) {                                             \
        int row = lrow + i * 64;                                              \
        CP_ASYNC16(st + sw_off(row, lc), g_xh + (size_t)(t0 + row) * DIM + (k0) + lc * 8); \
        CP_ASYNC16(st + 8192 + sw_off(row, lc), g_lAt + (size_t)row * DIM + (k0) + lc * 8); \
    }                                                                         \
    CP_COMMIT();                                                              \
} while (0)

    LA_ISSUE(0, 0);
    LA_ISSUE(1, 32);
    LA_ISSUE(2, 64);
    for (int c = 0; c < 64; c++) {
        if (c < 62) { CP_WAIT(2); } else if (c == 62) { CP_WAIT(1); } else { CP_WAIT(0); }
        __syncthreads();
        if (c + 3 < 64) LA_ISSUE((c + 3) & 3, (c + 3) * 32);
        uint32_t base = sb + (uint32_t)(c & 3) * LA_STAGE;
#pragma unroll
        for (int kk = 0; kk < 2; kk++) {
            uint32_t ah[2][4];
#pragma unroll
            for (int mi = 0; mi < 2; mi++) {
                int r = warp_m + mi * 16 + (lane & 15);
                ldsm4(ah[mi], base + sw_off(r, kk * 2 + (lane >> 4)));
            }
#pragma unroll
            for (int p = 0; p < 4; p++) {
                uint32_t bh[4];
                int r = warp_n + p * 16 + (lane & 7) + ((lane >> 4) << 3);
                ldsm4(bh, base + 8192 + sw_off(r, kk * 2 + ((lane >> 3) & 1)));
#pragma unroll
                for (int mi = 0; mi < 2; mi++) {
                    mma16816(acc[mi][p * 2], ah[mi], bh);
                    mma16816(acc[mi][p * 2 + 1], ah[mi], bh + 2);
                }
            }
        }
        __syncthreads();
    }

#pragma unroll
    for (int mi = 0; mi < 2; mi++) {
#pragma unroll
        for (int h = 0; h < 2; h++) {
            int t = t0 + warp_m + mi * 16 + (lane >> 2) + h * 8;
            int se = g_idx[t];
            float wv = g_w[t];
#pragma unroll
            for (int nt = 0; nt < 8; nt++) {
                int col = warp_n + nt * 8 + (lane & 3) * 2;
                float v0 = ((col >> 4) == se) ? wv * gelu_exact(acc[mi][nt][h * 2]) : 0.f;
                float v1 = (((col + 1) >> 4) == se) ? wv * gelu_exact(acc[mi][nt][h * 2 + 1]) : 0.f;
                __half2 p2 = __floats2half2_rn(v0, v1);
                *(uint32_t*)(g_hm + (size_t)t * ER + col) = *(uint32_t*)&p2;
            }
        }
    }
}

// ---------------- main kernel: out = gelu(x@W^T + b) + hm@lBt^T ----------------
#define ST_WH  8192
#define STAGE_B 16384

__global__ __launch_bounds__(256, 2) void main_mma(
    const float* __restrict__ bb, float* __restrict__ out)
{
    extern __shared__ char sm[];
    uint32_t sb = smem_u32(sm);
    const int tid = threadIdx.x, wid = tid >> 5, lane = tid & 31;
    const int n0 = blockIdx.x * 128, t0 = blockIdx.y * 128;
    const int warp_m = (wid & 3) * 32, warp_n = (wid >> 2) * 64;
    const int lrow = tid >> 2, lc = tid & 3;

    float acc[2][8][4];
#pragma unroll
    for (int a = 0; a < 2; a++)
#pragma unroll
        for (int b = 0; b < 8; b++)
#pragma unroll
            for (int c = 0; c < 4; c++) acc[a][b][c] = 0.f;

#define MN_ISSUE(s, k0) do {                                                  \
    uint32_t st = sb + (uint32_t)(s) * STAGE_B;                               \
    _Pragma("unroll")                                                         \
    for (int i = 0; i < 2; i++) {                                             \
        int row = lrow + i * 64;                                              \
        uint32_t so = sw_off(row, lc);                                        \
        CP_ASYNC16(st + so, g_xh + (size_t)(t0 + row) * DIM + (k0) + lc * 8); \
        CP_ASYNC16(st + ST_WH + so, g_wh + (size_t)(n0 + row) * DIM + (k0) + lc * 8); \
    }                                                                         \
    CP_COMMIT();                                                              \
} while (0)

    MN_ISSUE(0, 0);
    MN_ISSUE(1, 32);
    MN_ISSUE(2, 64);
    for (int c = 0; c < 64; c++) {
        if (c < 62) { CP_WAIT(2); } else if (c == 62) { CP_WAIT(1); } else { CP_WAIT(0); }
        __syncthreads();
        if (c + 3 < 64) MN_ISSUE((c + 3) & 3, (c + 3) * 32);
        uint32_t base = sb + (uint32_t)(c & 3) * STAGE_B;
#pragma unroll
        for (int kk = 0; kk < 2; kk++) {
            uint32_t ah[2][4];
#pragma unroll
            for (int mi = 0; mi < 2; mi++) {
                int r = warp_m + mi * 16 + (lane & 15);
                ldsm4(ah[mi], base + sw_off(r, kk * 2 + (lane >> 4)));
            }
#pragma unroll
            for (int p = 0; p < 4; p++) {
                uint32_t bh[4];
                int r = warp_n + p * 16 + (lane & 7) + ((lane >> 4) << 3);
                ldsm4(bh, base + ST_WH + sw_off(r, kk * 2 + ((lane >> 3) & 1)));
#pragma unroll
                for (int mi = 0; mi < 2; mi++) {
                    mma16816(acc[mi][p * 2],     ah[mi], bh);
                    mma16816(acc[mi][p * 2 + 1], ah[mi], bh + 2);
                }
            }
        }
        __syncthreads();
    }

    // ---- base epilogue: out = gelu(acc + bias) ----
#pragma unroll
    for (int mi = 0; mi < 2; mi++) {
#pragma unroll
        for (int h = 0; h < 2; h++) {
            int t = t0 + warp_m + mi * 16 + (lane >> 2) + h * 8;
            float* orow = out + (size_t)t * DIM + n0 + warp_n;
#pragma unroll
            for (int nt = 0; nt < 8; nt++) {
                int col = nt * 8 + (lane & 3) * 2;
                float b0 = __ldg(bb + n0 + warp_n + col);
                float b1 = __ldg(bb + n0 + warp_n + col + 1);
                float2 v;
                v.x = gelu_exact(acc[mi][nt][h * 2] + b0);
                v.y = gelu_exact(acc[mi][nt][h * 2 + 1] + b1);
                *(float2*)(orow + col) = v;
            }
        }
    }

    // ---- LoRA-B tail: acc = hm @ lBt^T (K=128), out += acc ----
#pragma unroll
    for (int a = 0; a < 2; a++)
#pragma unroll
        for (int b = 0; b < 8; b++)
#pragma unroll
            for (int c = 0; c < 4; c++) acc[a][b][c] = 0.f;

    for (int c2 = 0; c2 < 4; c2++) {
        int k0 = c2 * 32;
        __syncthreads();
#pragma unroll
        for (int i = 0; i < 2; i++) {
            int row = lrow + i * 64;
            uint32_t so = sw_off(row, lc);
            CP_ASYNC16(sb + so, g_hm + (size_t)(t0 + row) * ER + k0 + lc * 8);
            CP_ASYNC16(sb + ST_WH + so, g_lBt + (size_t)(n0 + row) * ER + k0 + lc * 8);
        }
        CP_COMMIT();
        CP_WAIT(0);
        __syncthreads();
#pragma unroll
        for (int kk = 0; kk < 2; kk++) {
            uint32_t ah[2][4];
#pragma unroll
            for (int mi = 0; mi < 2; mi++) {
                int r = warp_m + mi * 16 + (lane & 15);
                ldsm4(ah[mi], sb + sw_off(r, kk * 2 + (lane >> 4)));
            }
#pragma unroll
            for (int p = 0; p < 4; p++) {
                uint32_t bh[4];
                int r = warp_n + p * 16 + (lane & 7) + ((lane >> 4) << 3);
                ldsm4(bh, sb + ST_WH + sw_off(r, kk * 2 + ((lane >> 3) & 1)));
#pragma unroll
                for (int mi = 0; mi < 2; mi++) {
                    mma16816(acc[mi][p * 2], ah[mi], bh);
                    mma16816(acc[mi][p * 2 + 1], ah[mi], bh + 2);
                }
            }
        }
    }
#pragma unroll
    for (int mi = 0; mi < 2; mi++) {
#pragma unroll
        for (int h = 0; h < 2; h++) {
            int t = t0 + warp_m + mi * 16 + (lane >> 2) + h * 8;
            float* orow = out + (size_t)t * DIM + n0 + warp_n;
#pragma unroll
            for (int nt = 0; nt < 8; nt++) {
                int col = nt * 8 + (lane & 3) * 2;
                float2 v = *(float2*)(orow + col);
                v.x += acc[mi][nt][h * 2];
                v.y += acc[mi][nt][h * 2 + 1];
                *(float2*)(orow + col) = v;
            }
        }
    }
}

// ---------------------------------------------------------------------------
extern "C" void kernel_launch(void* const* d_in, const int* in_sizes, int n_in,
                              void* d_out, int out_size)
{
    const float* x  = (const float*)d_in[0];
    const float* gw = (const float*)d_in[1];
    const float* gb = (const float*)d_in[2];
    const float* bw = (const float*)d_in[3];
    const float* bb = (const float*)d_in[4];
    const float* lA = (const float*)d_in[5];
    const float* lB = (const float*)d_in[6];

    float* out   = (float*)d_out;
    float* probs = out + (size_t)T_TOK * (size_t)DIM;

    cudaFuncSetAttribute(convx_router, cudaFuncAttributeMaxDynamicSharedMemorySize, NE * DIM * 4);
    cudaFuncSetAttribute(main_mma, cudaFuncAttributeMaxDynamicSharedMemorySize, 4 * STAGE_B);
    cudaFuncSetAttribute(loraA_mma, cudaFuncAttributeMaxDynamicSharedMemorySize, 4 * LA_STAGE);

    convx_router<<<T_TOK / 8, 256, NE * DIM * 4>>>(x, gw, gb, probs);
    conv_w<<<DIM * DIM / 4 / 256, 256>>>(bw, DIM * DIM / 4);
    pack_lA_kernel<<<ER * DIM / 256, 256>>>(lA);
    pack_lB_kernel<<<DIM * ER / 256, 256>>>(lB);
    loraA_mma<<<T_TOK / 128, 256, 4 * LA_STAGE>>>();
    main_mma<<<dim3(DIM / 128, T_TOK / 128), 256, 4 * STAGE_B>>>(bb, out);
}